// round 17
// baseline (speedup 1.0000x reference)
#include <cuda_runtime.h>
#include <cuda_bf16.h>

// PairTabAtomicModel: tabulated pair potential atomic energy.
// Shapes (fixed):
//   extended_coord : [8, 16384, 3] f32
//   tab_data       : [4, 4, 2000, 4] f32
//   tab_info       : [4] f32  (rmin, hh, nspline, ntypes)
//   extended_atype : [8, 16384] i32      (0..3)
//   nlist          : [8, 8192, 128] i32
//   out            : [8, 8192, 1] f32
//
// Numerical contract (locked in R6, bit-matches XLA-GPU):
//   s2 = fma(dz,dz, fma(dx,dx, dy*dy)) ; rr = sqrt.rn(s2)
//   uu = div.full.f32(rr - rmin, hh)
//
// R13/R16 (35.3us): coords in SMEM with sign-bit type encoding; established
//   via R14 (ILP), R15 (LDS diet), R16 (prefetch) that the kernel is
//   INSTRUCTION-COUNT bound (~340 warp-instrs/row at issue 42%), not
//   latency/crossbar/occupancy bound.
// R17: instruction diet. Drop the sign-bit steganography: store xy/z as
//   plain floats + a separate u8 type array in smem (16 KB more, 208 KB
//   total). Removes ~6 decode ops per neighbor + per-row decode; type comes
//   from one batched unconditional LDS.U8.

#define NFRAMES 8
#define NLOC    8192
#define NNEI    128
#define NALL    16384
#define RCUT_F  6.0f

#define BLOCKS_PER_FRAME 37
#define ROWS_PER_BLOCK   222          // ceil(8192 / 37)
#define THREADS          1024
#define WARPS            (THREADS / 32)
// float2 xy[NALL] (128K) + float z[NALL] (64K) + u8 type[NALL] (16K) = 208K
#define SMEM_BYTES       (NALL * 3 * 4 + NALL)

__device__ __forceinline__ float div_full(float a, float b) {
    float r;
    asm("div.full.f32 %0, %1, %2;" : "=f"(r) : "f"(a), "f"(b));
    return r;
}

__global__ __launch_bounds__(THREADS, 1)
void pairtab_energy_smem_kernel(const float* __restrict__ coord,
                                const float* __restrict__ tab_data,
                                const float* __restrict__ tab_info,
                                const int*   __restrict__ atype,
                                const int*   __restrict__ nlist,
                                float*       __restrict__ out)
{
    extern __shared__ float sm[];
    float2*        __restrict__ xys = reinterpret_cast<float2*>(sm);     // [NALL]
    float*         __restrict__ zs  = sm + 2 * NALL;                     // [NALL]
    unsigned char* __restrict__ ts  =
        reinterpret_cast<unsigned char*>(sm + 3 * NALL);                 // [NALL]

    const int f    = blockIdx.x / BLOCKS_PER_FRAME;
    const int slot = blockIdx.x % BLOCKS_PER_FRAME;
    const int tid  = threadIdx.x;

    // ---- cooperative smem fill: coords (AoS->SoA) + type bytes ----
    {
        const float* __restrict__ cframe = coord + (size_t)f * NALL * 3;
        const int*   __restrict__ tframe = atype + (size_t)f * NALL;
        for (int i = tid; i < NALL; i += THREADS) {
            float2 v;
            v.x = cframe[3 * i + 0];
            v.y = cframe[3 * i + 1];
            xys[i] = v;
            zs[i]  = cframe[3 * i + 2];
            ts[i]  = (unsigned char)tframe[i];
        }
    }
    __syncthreads();

    const float rmin    = tab_info[0];
    const float hh      = tab_info[1];
    const int   nspline = (int)tab_info[2];
    const int   ntypes  = (int)tab_info[3];
    const float rmax    = __fadd_rn(rmin, __fmul_rn((float)nspline, hh));
    const float rcut_eff = (RCUT_F < rmax) ? RCUT_F : rmax;

    const int warp = tid >> 5;
    const int lane = tid & 31;

    const int row_begin = slot * ROWS_PER_BLOCK;
    int row_end = row_begin + ROWS_PER_BLOCK;
    if (row_end > NLOC) row_end = NLOC;

    for (int r = row_begin + warp; r < row_end; r += WARPS) {
        // own atom: plain loads, no decode
        const float2 cixy = xys[r];
        const float  xi = cixy.x;
        const float  yi = cixy.y;
        const float  zi = zs[r];
        const int    ti = ts[r];
        const float* __restrict__ tab_i =
            tab_data + (unsigned)(ti * ntypes * nspline * 4);

        const int4 jj = *reinterpret_cast<const int4*>(
            nlist + (size_t)(f * NLOC + r) * NNEI + lane * 4);
        const int js[4] = { jj.x, jj.y, jj.z, jj.w };

        // ---- stage 1: batch-issue all 4 coord+type gathers (unconditional) ----
        float2 cxy[4];
        float  cz[4];
        int    ct[4];
        #pragma unroll
        for (int k = 0; k < 4; k++) {
            const int s = js[k] >= 0 ? js[k] : 0;
            cxy[k] = xys[s];
            cz[k]  = zs[s];
            ct[k]  = ts[s];
        }

        // ---- stage 2: 4 independent rr chains (bit-exact path, locked) ----
        float rr[4];
        bool  act[4];
        #pragma unroll
        for (int k = 0; k < 4; k++) {
            const float dx = __fsub_rn(cxy[k].x, xi);
            const float dy = __fsub_rn(cxy[k].y, yi);
            const float dz = __fsub_rn(cz[k],   zi);
            const float s2 = __fmaf_rn(dz, dz,
                             __fmaf_rn(dx, dx,
                             __fmul_rn(dy, dy)));
            rr[k]  = __fsqrt_rn(s2);
            act[k] = (js[k] >= 0) && (rr[k] < rcut_eff);
        }

        // ---- stage 3: bin math + batch-issue 4 predicated tab gathers ----
        float  frac[4];
        float4 c[4];
        #pragma unroll
        for (int k = 0; k < 4; k++) {
            const float uu = div_full(__fsub_rn(rr[k], rmin), hh);
            const int   idx = (int)uu;             // trunc == astype(int32)
            frac[k] = __fsub_rn(uu, (float)idx);
            int clip = idx;
            if (clip < 0) clip = 0;
            if (clip > nspline - 1) clip = nspline - 1;
            c[k] = make_float4(0.f, 0.f, 0.f, 0.f);
            if (act[k]) {
                const unsigned off = (unsigned)(ct[k] * nspline + clip) << 2;
                c[k] = *reinterpret_cast<const float4*>(tab_i + off);
            }
        }

        // ---- stage 4: accumulate (inactive -> coefs 0 -> exact 0) ----
        float sum = 0.0f;
        #pragma unroll
        for (int k = 0; k < 4; k++)
            sum += ((c[k].x * frac[k] + c[k].y) * frac[k] + c[k].z) * frac[k] + c[k].w;

        // warp butterfly reduction
        #pragma unroll
        for (int off = 16; off > 0; off >>= 1)
            sum += __shfl_xor_sync(0xffffffffu, sum, off);

        if (lane == 0)
            out[f * NLOC + r] = 0.5f * sum;
    }
}

extern "C" void kernel_launch(void* const* d_in, const int* in_sizes, int n_in,
                              void* d_out, int out_size)
{
    const float* coord    = (const float*)d_in[0];
    const float* tab_data = (const float*)d_in[1];
    const float* tab_info = (const float*)d_in[2];
    const int*   atype    = (const int*)d_in[3];
    const int*   nlist    = (const int*)d_in[4];
    float*       out      = (float*)d_out;

    static bool attr_set = false;
    if (!attr_set) {
        cudaFuncSetAttribute(pairtab_energy_smem_kernel,
                             cudaFuncAttributeMaxDynamicSharedMemorySize,
                             SMEM_BYTES);
        attr_set = true;
    }

    const int blocks = NFRAMES * BLOCKS_PER_FRAME;   // 296 = 2 waves x 148 SMs
    pairtab_energy_smem_kernel<<<blocks, THREADS, SMEM_BYTES>>>(
        coord, tab_data, tab_info, atype, nlist, out);
}